// round 11
// baseline (speedup 1.0000x reference)
#include <cuda_runtime.h>
#include <cstdint>

// RSNALoss fused, phase-accumulation (no smem staging):
//  NT=160 threads (160 % 5 == 0). 2 rows = 20 floats = 5 float4, so thread t has
//  a FIXED phase = t%5 across all grid-stride steps, and the 4 channels in its
//  float4 are known per phase: ch(phase,slot) = (4*phase+slot) % 10.
//  Hot loop = 8 fully-unrolled predicated LDG.128 per tensor (perfect
//  coalescing, huge MLP, no syncs). ch0 BCE handled at (p0,s0)/(p2,s2).
//  Block epilogue: deterministic smem gather (fixed order) -> 20 partials.
//  Last block (atomic ticket) finalizes; ticket only selects the finalizer.

#define BATCH 128
#define SEQ   8192
#define NT    160
#define NITER 8
#define F4_TILE (NT * NITER)            // 1280 float4 = 512 rows
#define TILE_ROWS 512
#define BPB   (SEQ / TILE_ROWS)         // 16 tiles per batch
#define NBLK  (BATCH * BPB)             // 2048 blocks
#define NACC  20

#define IMAGE_WEIGHT 0.0736196319f

__constant__ float c_w[9] = {
    0.0736196319f, 0.09202453988f, 0.1042944785f, 0.1042944785f,
    0.1877300613f, 0.06257668712f, 0.06257668712f, 0.2346625767f,
    0.0782208589f
};

__device__ __align__(16) float g_partials[NACC * NBLK];  // [acc][b*BPB + tile]
__device__ unsigned int g_ticket;                        // zero-init; reset by last block

__global__ __launch_bounds__(NT)
void rsna_fused_kernel(const float* __restrict__ pred,
                       const float* __restrict__ label,
                       const int*   __restrict__ seq_lens,
                       float* __restrict__ out)
{
    const int b    = blockIdx.y;
    const int tile = blockIdx.x;
    const int t    = threadIdx.x;
    const int sl   = __ldg(&seq_lens[b]);
    const int phase = t % 5;

    const int T0 = tile * F4_TILE;          // float4 offset within this batch
    const int L  = sl * 10;                 // valid float count in this batch

    const float4* __restrict__ pg = (const float4*)(pred  + (size_t)b * SEQ * 10);
    const float4* __restrict__ lg = (const float4*)(label + (size_t)b * SEQ * 10);

    float pacc0 = 0.f, pacc1 = 0.f, pacc2 = 0.f, pacc3 = 0.f;
    float lacc0 = 0.f, lacc1 = 0.f, lacc2 = 0.f, lacc3 = 0.f;
    float bce = 0.f;

    if (T0 * 4 < L) {   // tile has at least one valid row
        float4 vp[NITER], vl[NITER];
#pragma unroll
        for (int k = 0; k < NITER; k++) {
            const int idx = T0 + t + k * NT;
            const int rem = L - 4 * idx;
            vp[k] = make_float4(0.f, 0.f, 0.f, 0.f);
            vl[k] = make_float4(0.f, 0.f, 0.f, 0.f);
            if (rem > 0) { vp[k] = pg[idx]; vl[k] = lg[idx]; }
        }
#pragma unroll
        for (int k = 0; k < NITER; k++) {
            const int idx = T0 + t + k * NT;
            const int rem = L - 4 * idx;
            float4 p = vp[k], l = vl[k];
            // zero tail elements past the valid limit (partial float4)
            if (rem < 4) {
                p.y = (rem > 1) ? p.y : 0.f;  l.y = (rem > 1) ? l.y : 0.f;
                p.z = (rem > 2) ? p.z : 0.f;  l.z = (rem > 2) ? l.z : 0.f;
                p.w = (rem > 3) ? p.w : 0.f;  l.w = (rem > 3) ? l.w : 0.f;
            }
            pacc0 += p.x; pacc1 += p.y; pacc2 += p.z; pacc3 += p.w;
            lacc0 += l.x; lacc1 += l.y; lacc2 += l.z; lacc3 += l.w;

            // channel-0 BCE lives at (phase0,slot0) and (phase2,slot2)
            if (phase == 0 || phase == 2) {
                const float p0v = (phase == 0) ? p.x : p.z;
                const float y0v = (phase == 0) ? l.x : l.z;
                const bool  ev  = (phase == 0) ? (rem > 0) : (rem > 2);
                const float term = -(y0v * __logf(p0v) +
                                     (1.0f - y0v) * __logf(1.0f - p0v));
                bce += ev ? term : 0.f;
            }
        }
    }

    // ---- deterministic block gather: (phase,slot) -> 20 channel sums ----
    __shared__ float s_p[NT][4];
    __shared__ float s_l[NT][4];
    __shared__ float s_b[NT];
    s_p[t][0] = pacc0; s_p[t][1] = pacc1; s_p[t][2] = pacc2; s_p[t][3] = pacc3;
    s_l[t][0] = lacc0; s_l[t][1] = lacc1; s_l[t][2] = lacc2; s_l[t][3] = lacc3;
    s_b[t] = bce;
    __syncthreads();

    // acc layout: 0..8 = pred ch1..9 | 9..17 = label ch1..9 | 18 = label ch0 | 19 = bce
    if (t < NACC) {
        float s = 0.f;
        if (t == 19) {
            for (int j = 0; j < NT; j++) s += s_b[j];
        } else {
            const bool is_pred = (t < 9);
            const int  c = is_pred ? (t + 1) : ((t < 18) ? (t - 8) : 0);
#pragma unroll
            for (int pp = 0; pp < 5; pp++) {
                const int sidx = ((c - 4 * pp) % 10 + 10) % 10;
                if (sidx < 4) {
                    for (int j = 0; j < 32; j++) {
                        const int th = pp + 5 * j;
                        s += is_pred ? s_p[th][sidx] : s_l[th][sidx];
                    }
                }
            }
        }
        g_partials[t * NBLK + b * BPB + tile] = s;   // accumulator-major
    }

    // ---- ticket: last finished block finalizes ----
    __shared__ int s_last;
    __threadfence();
    __syncthreads();
    if (t == 0) {
        unsigned int tk = atomicAdd(&g_ticket, 1u);
        s_last = (tk == (unsigned int)(NBLK - 1)) ? 1 : 0;
    }
    __syncthreads();
    if (!s_last) return;

    if (t == 0) g_ticket = 0;
    __threadfence();

    // ---- finalize: thread b (<128) handles batch b; L2-hot coalesced float4 ----
    float num = 0.f, wsum = 0.f;
    if (t < BATCH) {
        const float4* gp = (const float4*)g_partials;
        float a[NACC];
#pragma unroll
        for (int i = 0; i < NACC; i++) {
            float s = 0.f;
#pragma unroll
            for (int j = 0; j < BPB / 4; j++) {        // 4 x float4 = 16 partials
                float4 v = gp[i * (NBLK / 4) + t * (BPB / 4) + j];
                s += ((v.x + v.y) + (v.z + v.w));
            }
            a[i] = s;
        }

        const float len = (float)__ldg(&seq_lens[t]);
        const float inv = 1.0f / len;

        float exam = 0.f;
#pragma unroll
        for (int c = 0; c < 9; c++) {
            const float pm = a[c]     * inv;
            const float ym = a[9 + c] * inv;
            exam += c_w[c] * (-(ym * __logf(pm) + (1.0f - ym) * __logf(1.0f - pm)));
        }

        const float y0m = a[18] * inv;
        const float iw  = IMAGE_WEIGHT * y0m;
        num  = exam + a[19] * iw;
        wsum = iw * len;
    }

#pragma unroll
    for (int off = 16; off > 0; off >>= 1) {
        num  += __shfl_xor_sync(0xFFFFFFFFu, num,  off);
        wsum += __shfl_xor_sync(0xFFFFFFFFu, wsum, off);
    }
    __shared__ float s_num[NT / 32], s_ws[NT / 32];
    const int wid  = t >> 5;
    const int lane = t & 31;
    if (lane == 0) { s_num[wid] = num; s_ws[wid] = wsum; }
    __syncthreads();
    if (t == 0) {
        float n = 0.f, w = 0.f;
#pragma unroll
        for (int i = 0; i < NT / 32; i++) { n += s_num[i]; w += s_ws[i]; }
        float sumw = 0.f;
#pragma unroll
        for (int c = 0; c < 9; c++) sumw += c_w[c];
        out[0] = n / ((float)BATCH * sumw + w);
    }
}

extern "C" void kernel_launch(void* const* d_in, const int* in_sizes, int n_in,
                              void* d_out, int out_size)
{
    const float* pred  = (const float*)d_in[0];
    const float* label = (const float*)d_in[1];
    const int*   slens = (const int*)d_in[2];
    float* out = (float*)d_out;

    dim3 grid(BPB, BATCH);
    rsna_fused_kernel<<<grid, NT>>>(pred, label, slens, out);
}

// round 12
// speedup vs baseline: 1.5647x; 1.5647x over previous
#include <cuda_runtime.h>
#include <cstdint>

// RSNALoss fused, smem-staged, INTERLEAVED chunk assignment:
//  1024 blocks (128 thr) = 8 slots/batch x 128 batches. Block (b,slot) processes
//  chunks slot, slot+8, slot+16, ... (128 rows each, contiguous within a chunk),
//  double-buffered cp.async (coalesced 16B copies). Round-robin dealing makes
//  every block of a batch do within +-1 chunk of equal work -> per-SM work ~= mean
//  (kills the single-wave max-over-SMs imbalance that capped DRAM at ~33%).
//  Last block (atomic ticket) finalizes. Deterministic: ticket only selects the
//  finalizing block; the partial array it reads is complete and fixed.

#define BATCH 128
#define SEQ   8192
#define NT    128
#define CHUNK 128                       // rows per chunk (== NT)
#define CH10  (CHUNK * 10)              // 1280 floats per tensor per chunk
#define F4PT  (CH10 / 4)                // 320 float4 per tensor per chunk
#define SLOTS 8                         // blocks per batch
#define MAXCH 8                         // max chunks per block (64 chunks / 8 slots)
#define NBLK  (BATCH * SLOTS)           // 1024 blocks
#define NACC  20
#define NWARP (NT / 32)

#define IMAGE_WEIGHT 0.0736196319f

__constant__ float c_w[9] = {
    0.0736196319f, 0.09202453988f, 0.1042944785f, 0.1042944785f,
    0.1877300613f, 0.06257668712f, 0.06257668712f, 0.2346625767f,
    0.0782208589f
};

__device__ __align__(16) float g_partials[NACC * NBLK];  // [acc][b*SLOTS + slot]
__device__ unsigned int g_ticket;                        // zero-init; reset by last block

__device__ __forceinline__ void cp16(uint32_t s, const void* g, bool p)
{
    asm volatile(
        "{ .reg .pred q; setp.ne.u32 q, %2, 0;"
        "  @q cp.async.cg.shared.global [%0], [%1], 16; }"
        :: "r"(s), "l"(g), "r"((int)p));
}

__global__ __launch_bounds__(NT, 10)
void rsna_fused_kernel(const float* __restrict__ pred,
                       const float* __restrict__ label,
                       const int*   __restrict__ seq_lens,
                       float* __restrict__ out)
{
    const int b    = blockIdx.y;
    const int slot = blockIdx.x;
    const int tid  = threadIdx.x;
    const int sl   = __ldg(&seq_lens[b]);

    __shared__ __align__(16) float s_pred[2][CH10];
    __shared__ __align__(16) float s_lab [2][CH10];

    float acc[NACC];
#pragma unroll
    for (int i = 0; i < NACC; i++) acc[i] = 0.0f;

    // chunks of batch b: 0..nct-1; this block takes slot, slot+8, slot+16, ...
    const int nct = (sl + CHUNK - 1) / CHUNK;              // 1..64
    int nch = (nct - slot + SLOTS - 1) / SLOTS;            // may be <=0
    nch = max(0, min(nch, MAXCH));

    const float* pbase = pred  + (size_t)b * SEQ * 10;
    const float* lbase = label + (size_t)b * SEQ * 10;

    auto prefetch = [&](int c, int buf) {
        const int cb  = (slot + c * SLOTS) * CHUNK;        // interleaved chunk base row
        const int lim = (sl - cb) * 10;                    // valid floats in this chunk
        const float4* pg = (const float4*)(pbase + (size_t)cb * 10);
        const float4* lg = (const float4*)(lbase + (size_t)cb * 10);
        const uint32_t sp = (uint32_t)__cvta_generic_to_shared(&s_pred[buf][0]);
        const uint32_t sy = (uint32_t)__cvta_generic_to_shared(&s_lab [buf][0]);
#pragma unroll
        for (int j = 0; j < 5; j++) {       // 640 float4 over 128 threads
            const int idx = tid + j * NT;
            if (idx < F4PT) {
                cp16(sp + idx * 16, pg + idx, (idx * 4) < lim);
            } else {
                const int i2 = idx - F4PT;
                cp16(sy + i2 * 16, lg + i2, (i2 * 4) < lim);
            }
        }
        asm volatile("cp.async.commit_group;");
    };

    if (nch > 0) prefetch(0, 0);

    for (int c = 0; c < nch; c++) {
        if (c + 1 < nch) {
            prefetch(c + 1, (c + 1) & 1);
            asm volatile("cp.async.wait_group 1;");
        } else {
            asm volatile("cp.async.wait_group 0;");
        }
        __syncthreads();

        const int row = (slot + c * SLOTS) * CHUNK + tid;
        if (row < sl) {
            const float2* pr = (const float2*)&s_pred[c & 1][tid * 10];
            const float2* lr = (const float2*)&s_lab [c & 1][tid * 10];
            float2 p0 = pr[0], p1 = pr[1], p2 = pr[2], p3 = pr[3], p4 = pr[4];
            float2 l0 = lr[0], l1 = lr[1], l2 = lr[2], l3 = lr[3], l4 = lr[4];

            acc[0] += p0.y; acc[1] += p1.x; acc[2] += p1.y; acc[3] += p2.x;
            acc[4] += p2.y; acc[5] += p3.x; acc[6] += p3.y; acc[7] += p4.x;
            acc[8] += p4.y;

            acc[9]  += l0.y; acc[10] += l1.x; acc[11] += l1.y; acc[12] += l2.x;
            acc[13] += l2.y; acc[14] += l3.x; acc[15] += l3.y; acc[16] += l4.x;
            acc[17] += l4.y;

            const float p0v = p0.x, y0v = l0.x;
            acc[18] += y0v;
            acc[19] += -(y0v * __logf(p0v) + (1.0f - y0v) * __logf(1.0f - p0v));
        }
        __syncthreads();   // buffer (c&1) is rewritten by prefetch(c+2)
    }

    // ---- warp + block reduce the 20 accumulators ----
#pragma unroll
    for (int i = 0; i < NACC; i++) {
#pragma unroll
        for (int off = 16; off > 0; off >>= 1)
            acc[i] += __shfl_xor_sync(0xFFFFFFFFu, acc[i], off);
    }

    __shared__ float s_red[NWARP * NACC];
    const int wid  = tid >> 5;
    const int lane = tid & 31;
    if (lane == 0) {
#pragma unroll
        for (int i = 0; i < NACC; i++) s_red[wid * NACC + i] = acc[i];
    }
    __syncthreads();

    if (tid < NACC) {
        float s = 0.0f;
#pragma unroll
        for (int w = 0; w < NWARP; w++) s += s_red[w * NACC + tid];
        g_partials[tid * NBLK + b * SLOTS + slot] = s;   // accumulator-major
    }

    // ---- ticket: last finished block finalizes ----
    __shared__ int s_last;
    __threadfence();
    __syncthreads();
    if (tid == 0) {
        unsigned int t = atomicAdd(&g_ticket, 1u);
        s_last = (t == (unsigned int)(NBLK - 1)) ? 1 : 0;
    }
    __syncthreads();
    if (!s_last) return;

    if (tid == 0) g_ticket = 0;
    __threadfence();

    // ---- Phase 2: thread b (<128) finalizes batch b; L2-hot coalesced float4 ----
    float num = 0.0f, wsum = 0.0f;
    if (tid < BATCH) {
        const float4* gp = (const float4*)g_partials;
        float a[NACC];
#pragma unroll
        for (int i = 0; i < NACC; i++) {
            float4 x = gp[i * (NBLK / 4) + tid * 2];
            float4 y = gp[i * (NBLK / 4) + tid * 2 + 1];
            a[i] = ((x.x + x.y) + (x.z + x.w)) + ((y.x + y.y) + (y.z + y.w));
        }

        const float len = (float)__ldg(&seq_lens[tid]);
        const float inv = 1.0f / len;

        float exam = 0.0f;
#pragma unroll
        for (int c = 0; c < 9; c++) {
            const float pm = a[c]     * inv;
            const float ym = a[9 + c] * inv;
            exam += c_w[c] * (-(ym * __logf(pm) + (1.0f - ym) * __logf(1.0f - pm)));
        }

        const float y0m = a[18] * inv;
        const float iw  = IMAGE_WEIGHT * y0m;
        num  = exam + a[19] * iw;
        wsum = iw * len;
    }

#pragma unroll
    for (int off = 16; off > 0; off >>= 1) {
        num  += __shfl_xor_sync(0xFFFFFFFFu, num,  off);
        wsum += __shfl_xor_sync(0xFFFFFFFFu, wsum, off);
    }
    __shared__ float s_num[NWARP], s_ws[NWARP];
    if (lane == 0) { s_num[wid] = num; s_ws[wid] = wsum; }
    __syncthreads();
    if (tid == 0) {
        float n = 0.0f, w = 0.0f;
#pragma unroll
        for (int i = 0; i < NWARP; i++) { n += s_num[i]; w += s_ws[i]; }
        float sumw = 0.0f;
#pragma unroll
        for (int c = 0; c < 9; c++) sumw += c_w[c];
        out[0] = n / ((float)BATCH * sumw + w);
    }
}

extern "C" void kernel_launch(void* const* d_in, const int* in_sizes, int n_in,
                              void* d_out, int out_size)
{
    const float* pred  = (const float*)d_in[0];
    const float* label = (const float*)d_in[1];
    const int*   slens = (const int*)d_in[2];
    float* out = (float*)d_out;

    dim3 grid(SLOTS, BATCH);
    rsna_fused_kernel<<<grid, NT>>>(pred, label, slens, out);
}